// round 13
// baseline (speedup 1.0000x reference)
#include <cuda_runtime.h>
#include <cuda_fp16.h>
#include <cstdint>

#define ND 128
static const int MAXN = 50000;
static const int MAXE = 800000;

#define LDA 136                       // padded row length (fp16 elems)
#define LDAB (LDA * 2)                // 272 bytes per row
#define MAT_ELEMS (128 * LDA)         // 17408
#define MAT_BYTES (MAT_ELEMS * 2)     // 34816
#define NLAYER 8

// Scratch (device globals; allocation-free rule). Activations fp16.
__device__ __align__(16) __half g_h0[MAXN * ND];
__device__ float g_dinv[MAXN];
__device__ int   g_cnt[MAXN];
__device__ int   g_off[MAXN + 1];
__device__ int   g_cur[MAXN];
__device__ int   g_csr[MAXE];
__device__ int   g_bsum[128];
__device__ __align__(16) __half g_wsplit[NLAYER * 2 * MAT_ELEMS];

// ---------------------------------------------------------------------------
// Helpers
// ---------------------------------------------------------------------------
__device__ __forceinline__ uint32_t smem_u32(const void* p) {
    uint32_t a;
    asm("{ .reg .u64 t; cvta.to.shared.u64 t, %1; cvt.u32.u64 %0, t; }"
        : "=r"(a) : "l"(p));
    return a;
}

__device__ __forceinline__ void ldsm_x4(uint32_t& r0, uint32_t& r1,
                                        uint32_t& r2, uint32_t& r3, uint32_t addr) {
    asm volatile("ldmatrix.sync.aligned.m8n8.x4.shared.b16 {%0,%1,%2,%3}, [%4];"
                 : "=r"(r0), "=r"(r1), "=r"(r2), "=r"(r3) : "r"(addr));
}

__device__ __forceinline__ void mma16816(float& c0, float& c1, float& c2, float& c3,
                                         uint32_t a0, uint32_t a1, uint32_t a2, uint32_t a3,
                                         uint32_t b0, uint32_t b1) {
    asm volatile(
        "mma.sync.aligned.m16n8k16.row.col.f32.f16.f16.f32 "
        "{%0,%1,%2,%3}, {%4,%5,%6,%7}, {%8,%9}, {%0,%1,%2,%3};"
        : "+f"(c0), "+f"(c1), "+f"(c2), "+f"(c3)
        : "r"(a0), "r"(a1), "r"(a2), "r"(a3), "r"(b0), "r"(b1));
}

__device__ __forceinline__ uint32_t pack_h2(float a, float b) {
    __half ha = __float2half_rn(a), hb = __float2half_rn(b);
    return (uint32_t)__half_as_ushort(ha) |
           ((uint32_t)__half_as_ushort(hb) << 16);
}

__device__ __forceinline__ float sigmoidf_(float y) {
    return __fdividef(1.0f, 1.0f + __expf(-y));
}
__device__ __forceinline__ float softplus5f_(float y) {
    float t = y - 5.0f;
    return fmaxf(t, 0.0f) + log1pf(__expf(-fabsf(t)));
}

// ---------------------------------------------------------------------------
// W prep: per layer l, W^T split into fp16 hi/lo, padded ldmatrix layout.
// Layers: 0=gcn, 1..5=enc[i], 6=mean, 7=std. (lo used only by heads)
// ---------------------------------------------------------------------------
__global__ void wprep_kernel(const float* __restrict__ gcn,
                             const float* __restrict__ enc,
                             const float* __restrict__ meanw,
                             const float* __restrict__ stdw,
                             __half* __restrict__ dst)
{
    int l = blockIdx.y;
    const float* W = (l == 0) ? gcn
                   : (l <= 5) ? enc + (l - 1) * ND * ND
                   : (l == 6) ? meanw : stdw;
    int i = blockIdx.x * blockDim.x + threadIdx.x;
    int nn = i >> 7, k = i & 127;
    float w = W[k * ND + nn];
    __half hi = __float2half_rn(w);
    __half lo = __float2half_rn(w - __half2float(hi));
    __half* base = dst + (size_t)l * 2 * MAT_ELEMS;
    base[nn * LDA + k] = hi;
    base[MAT_ELEMS + nn * LDA + k] = lo;
}

// ---------------------------------------------------------------------------
// MMA body, warp tile 32x32 (accumulating).
// ---------------------------------------------------------------------------
__device__ __forceinline__ void mma_accum(uint32_t a_base, uint32_t Bb,
                                          float c[2][4][4])
{
#pragma unroll
    for (int ks = 0; ks < 8; ks++) {
        const uint32_t kb = (uint32_t)(ks * 16) * 2;
        uint32_t a[2][4];
#pragma unroll
        for (int mt = 0; mt < 2; mt++)
            ldsm_x4(a[mt][0], a[mt][1], a[mt][2], a[mt][3],
                    a_base + (uint32_t)(mt * 16) * LDAB + kb);
        uint32_t b[2][4];
#pragma unroll
        for (int q = 0; q < 2; q++)
            ldsm_x4(b[q][0], b[q][1], b[q][2], b[q][3],
                    Bb + (uint32_t)(q * 16) * LDAB + kb);
#pragma unroll
        for (int mt = 0; mt < 2; mt++)
#pragma unroll
            for (int nt = 0; nt < 4; nt++) {
                uint32_t b0 = b[nt >> 1][nt & 1];
                uint32_t b1 = b[nt >> 1][(nt & 1) + 2];
                mma16816(c[mt][nt][0], c[mt][nt][1], c[mt][nt][2], c[mt][nt][3],
                         a[mt][0], a[mt][1], a[mt][2], a[mt][3], b0, b1);
            }
    }
}

__device__ __forceinline__ void zero_c(float c[2][4][4]) {
#pragma unroll
    for (int mt = 0; mt < 2; mt++)
#pragma unroll
        for (int nt = 0; nt < 4; nt++)
#pragma unroll
            for (int i = 0; i < 4; i++) c[mt][nt][i] = 0.0f;
}

// ---------------------------------------------------------------------------
// Layout: CTA 64x128, 256 threads, 8 warps (2m x 4n), warp tile 32x32.
// mega smem: A[64][136] (17408) + W buf0 (34816) + W buf1 (34816) = 87040 B
// -> 2 CTAs/SM.
// ---------------------------------------------------------------------------
#define SM_A 0
#define SM_W0 17408
#define SM_W1 52224
#define SMEM_G 87040

// Sync copy of one hi matrix (2176 uint4) -- used by gemm_f32in.
__device__ __forceinline__ void copy_w_hi(char* smem, uint32_t dst_off,
                                          const __half* src, int t) {
    const uint4* s = reinterpret_cast<const uint4*>(src);
    uint4* d = reinterpret_cast<uint4*>(smem + dst_off);
#pragma unroll
    for (int i = 0; i < 8; i++) d[t + 256 * i] = s[t + 256 * i];
    if (t < 128) d[t + 2048] = s[t + 2048];
}

// Async copy of one hi matrix (2176 uint4) + commit group.
__device__ __forceinline__ void copy_w_async(uint32_t dst, const __half* src, int t) {
#pragma unroll
    for (int i = 0; i < 8; i++) {
        asm volatile("cp.async.cg.shared.global [%0], [%1], 16;"
                     :: "r"(dst + (uint32_t)(t + 256 * i) * 16),
                        "l"(src + (size_t)(t + 256 * i) * 8) : "memory");
    }
    if (t < 128) {
        asm volatile("cp.async.cg.shared.global [%0], [%1], 16;"
                     :: "r"(dst + (uint32_t)(t + 2048) * 16),
                        "l"(src + (size_t)(t + 2048) * 8) : "memory");
    }
    asm volatile("cp.async.commit_group;" ::: "memory");
}

#define CP_WAIT(N) asm volatile("cp.async.wait_group %0;" :: "n"(N) : "memory")

// ---- Layer 0: fp32 X -> fp16 Y (1-term, no bias/act) ----
__global__ void __launch_bounds__(256, 2)
gemm_f32in(const float* __restrict__ X, const __half* __restrict__ Bpre,
           __half* __restrict__ Y, int n)
{
    extern __shared__ char smem[];
    const uint32_t sb = smem_u32(smem);
    const int t = threadIdx.x;
    const int lane = t & 31, wid = t >> 5;
    const int warp_m = wid >> 2, warp_n = wid & 3;
    const int row0 = blockIdx.x * 64;

    copy_w_hi(smem, SM_W0, Bpre, t);
    {
        const float4* Xg = reinterpret_cast<const float4*>(X + (size_t)row0 * ND);
#pragma unroll
        for (int it = 0; it < 8; it++) {
            int idx = t + it * 256;
            int row = idx >> 5, kq = idx & 31;
            float4 v = make_float4(0.f, 0.f, 0.f, 0.f);
            if (row0 + row < n) v = Xg[(size_t)row * 32 + kq];
            uint32_t o = (uint32_t)row * LDAB + (uint32_t)kq * 8;
            *reinterpret_cast<uint2*>(smem + SM_A + o) =
                make_uint2(pack_h2(v.x, v.y), pack_h2(v.z, v.w));
        }
    }
    __syncthreads();

    const uint32_t lrow = (uint32_t)(lane & 15);
    const uint32_t lk = (uint32_t)((lane >> 4) * 8) * 2;
    const uint32_t a_base = sb + SM_A + ((uint32_t)(warp_m * 32) + lrow) * LDAB + lk;
    const uint32_t b_off = ((uint32_t)(warp_n * 32) + lrow) * LDAB + lk;

    float c[2][4][4];
    zero_c(c);
    mma_accum(a_base, sb + SM_W0 + b_off, c);

    const int rbase = row0 + warp_m * 32 + (lane >> 2);
    const int cbase = warp_n * 32 + (lane & 3) * 2;
#pragma unroll
    for (int mt = 0; mt < 2; mt++)
#pragma unroll
        for (int half = 0; half < 2; half++) {
            int row = rbase + mt * 16 + half * 8;
            if (row < n) {
#pragma unroll
                for (int nt = 0; nt < 4; nt++) {
                    int col = cbase + nt * 8;
                    *reinterpret_cast<uint32_t*>(Y + (size_t)row * ND + col) =
                        pack_h2(c[mt][nt][2 * half + 0], c[mt][nt][2 * half + 1]);
                }
            }
        }
}

// ---------------------------------------------------------------------------
// Threefry-2x32 (JAX partitionable), key = (0, 42)
// ---------------------------------------------------------------------------
__device__ __forceinline__ uint32_t rotl32(uint32_t x, int r) {
    return (x << r) | (x >> (32 - r));
}

__device__ __forceinline__ float tf_uniform(uint32_t i) {
    uint32_t x0 = 0u, x1 = i;
    const uint32_t k0 = 0u, k1 = 42u, k2 = 0u ^ 42u ^ 0x1BD11BDAu;
    x0 += k0; x1 += k1;
#define TF_ROUND(r) { x0 += x1; x1 = rotl32(x1, r); x1 ^= x0; }
    TF_ROUND(13) TF_ROUND(15) TF_ROUND(26) TF_ROUND(6)
    x0 += k1; x1 += k2 + 1u;
    TF_ROUND(17) TF_ROUND(29) TF_ROUND(16) TF_ROUND(24)
    x0 += k2; x1 += k0 + 2u;
    TF_ROUND(13) TF_ROUND(15) TF_ROUND(26) TF_ROUND(6)
    x0 += k0; x1 += k1 + 3u;
    TF_ROUND(17) TF_ROUND(29) TF_ROUND(16) TF_ROUND(24)
    x0 += k1; x1 += k2 + 4u;
    TF_ROUND(13) TF_ROUND(15) TF_ROUND(26) TF_ROUND(6)
    x0 += k2; x1 += k0 + 5u;
#undef TF_ROUND
    uint32_t bits = x0 ^ x1;
    return __uint_as_float((bits >> 9) | 0x3f800000u) - 1.0f;
}

// ---------------------------------------------------------------------------
// Megakernel @ 2 CTAs/SM with fused GCN gather prologue + cp.async
// double-buffered weights:
//   gather(h0,CSR) -> A smem -> 5 sigmoid layers (1-term, in-place A)
//   -> heads (2-term over 4 accumulate passes) -> fused z epilogue.
// Buffer schedule (B0/B1): prologue W1->B0, W2->B1; layer j consumes B[j&1]
// and refills it; heads consume WmHi(B1), WmLo(B0), WsHi(B1), WsLo(B0).
// ---------------------------------------------------------------------------
__global__ void __launch_bounds__(256, 2)
mega(const __half* __restrict__ h0, const float* __restrict__ dinv,
     const int* __restrict__ off, const int* __restrict__ csr,
     const float* __restrict__ gcn_b,
     const __half* __restrict__ ws, const float* __restrict__ enc_b,
     const float* __restrict__ bm, const float* __restrict__ bs,
     float* __restrict__ zo, float* __restrict__ muo, float* __restrict__ sto,
     int n)
{
    extern __shared__ char smem[];
    const uint32_t sb = smem_u32(smem);
    const int t = threadIdx.x;
    const int lane = t & 31, wid = t >> 5;
    const int warp_m = wid >> 2, warp_n = wid & 3;
    const int row0 = blockIdx.x * 64;

#define W_HI(l) (ws + (size_t)(l) * 2 * MAT_ELEMS)
#define W_LO(l) (ws + (size_t)(l) * 2 * MAT_ELEMS + MAT_ELEMS)

    // Prefetch W1 -> B0, W2 -> B1 first; the gather below overlaps the copies.
    copy_w_async(sb + SM_W0, W_HI(1), t);
    copy_w_async(sb + SM_W1, W_HI(2), t);

    // ---- Fused gather: warp w owns tile rows w*8..w*8+7 (lane = 4 cols) ----
    {
        const uint2* H0 = reinterpret_cast<const uint2*>(h0);
        float4 bb = reinterpret_cast<const float4*>(gcn_b)[lane];
        for (int r = 0; r < 8; r++) {
            int lr = wid * 8 + r;
            int node = row0 + lr;
            uint2 outv = make_uint2(0u, 0u);
            if (node < n) {
                float di = dinv[node];
                uint2 sv = H0[(size_t)node * 32 + lane];
                float2 s0 = __half22float2(*reinterpret_cast<__half2*>(&sv.x));
                float2 s1 = __half22float2(*reinterpret_cast<__half2*>(&sv.y));
                float dii = di * di;
                float a0 = s0.x * dii, a1 = s0.y * dii;
                float a2 = s1.x * dii, a3 = s1.y * dii;

                int j = off[node], end = off[node + 1];
                for (; j + 3 < end; j += 4) {
                    int r0 = csr[j], r1 = csr[j + 1];
                    int r2 = csr[j + 2], r3 = csr[j + 3];
                    float n0 = dinv[r0] * di, n1 = dinv[r1] * di;
                    float n2 = dinv[r2] * di, n3 = dinv[r3] * di;
                    uint2 v0 = H0[(size_t)r0 * 32 + lane];
                    uint2 v1 = H0[(size_t)r1 * 32 + lane];
                    uint2 v2 = H0[(size_t)r2 * 32 + lane];
                    uint2 v3 = H0[(size_t)r3 * 32 + lane];
                    float2 p, q;
                    p = __half22float2(*reinterpret_cast<__half2*>(&v0.x));
                    q = __half22float2(*reinterpret_cast<__half2*>(&v0.y));
                    a0 += n0 * p.x; a1 += n0 * p.y; a2 += n0 * q.x; a3 += n0 * q.y;
                    p = __half22float2(*reinterpret_cast<__half2*>(&v1.x));
                    q = __half22float2(*reinterpret_cast<__half2*>(&v1.y));
                    a0 += n1 * p.x; a1 += n1 * p.y; a2 += n1 * q.x; a3 += n1 * q.y;
                    p = __half22float2(*reinterpret_cast<__half2*>(&v2.x));
                    q = __half22float2(*reinterpret_cast<__half2*>(&v2.y));
                    a0 += n2 * p.x; a1 += n2 * p.y; a2 += n2 * q.x; a3 += n2 * q.y;
                    p = __half22float2(*reinterpret_cast<__half2*>(&v3.x));
                    q = __half22float2(*reinterpret_cast<__half2*>(&v3.y));
                    a0 += n3 * p.x; a1 += n3 * p.y; a2 += n3 * q.x; a3 += n3 * q.y;
                }
                for (; j < end; j++) {
                    int rr = csr[j];
                    float nr = dinv[rr] * di;
                    uint2 v = H0[(size_t)rr * 32 + lane];
                    float2 p = __half22float2(*reinterpret_cast<__half2*>(&v.x));
                    float2 q = __half22float2(*reinterpret_cast<__half2*>(&v.y));
                    a0 += nr * p.x; a1 += nr * p.y; a2 += nr * q.x; a3 += nr * q.y;
                }
                outv.x = pack_h2(a0 + bb.x, a1 + bb.y);
                outv.y = pack_h2(a2 + bb.z, a3 + bb.w);
            }
            *reinterpret_cast<uint2*>(
                smem + SM_A + (uint32_t)lr * LDAB + (uint32_t)lane * 8) = outv;
        }
    }

    const uint32_t lrow = (uint32_t)(lane & 15);
    const uint32_t lk = (uint32_t)((lane >> 4) * 8) * 2;
    const uint32_t a_base = sb + SM_A + ((uint32_t)(warp_m * 32) + lrow) * LDAB + lk;
    const uint32_t b_off = ((uint32_t)(warp_n * 32) + lrow) * LDAB + lk;
    const uint32_t WB[2] = {sb + SM_W0 + b_off, sb + SM_W1 + b_off};
    const uint32_t WDST[2] = {sb + SM_W0, sb + SM_W1};

    const int rloc = warp_m * 32 + (lane >> 2);
    const int cbase = warp_n * 32 + (lane & 3) * 2;

    // Prefetch order after the prologue, issued into the just-freed buffer:
    // j=0:W3, j=1:W4, j=2:W5, j=3:WmHi, j=4:WmLo; heads: WsHi, WsLo.
    const __half* nextW[5] = {W_HI(3), W_HI(4), W_HI(5), W_HI(6), W_LO(6)};

    // ---- 5 encoder layers ----
    for (int j = 0; j < 5; j++) {
        CP_WAIT(1);                   // current buffer's copy complete
        __syncthreads();              // visible to all warps; A ready (j=0)

        float c[2][4][4];
        zero_c(c);
        mma_accum(a_base, WB[j & 1], c);
        __syncthreads();              // all reads of A and W[j&1] done

        // Refill freed buffer; epilogue in parallel with the async copy.
        copy_w_async(WDST[j & 1], nextW[j], t);

        const float* bl = enc_b + j * ND;
#pragma unroll
        for (int mt = 0; mt < 2; mt++)
#pragma unroll
            for (int half = 0; half < 2; half++) {
                int lr = rloc + mt * 16 + half * 8;
#pragma unroll
                for (int nt = 0; nt < 4; nt++) {
                    int col = cbase + nt * 8;
                    float2 bb = *reinterpret_cast<const float2*>(bl + col);
                    float y0 = sigmoidf_(c[mt][nt][2 * half + 0] + bb.x);
                    float y1 = sigmoidf_(c[mt][nt][2 * half + 1] + bb.y);
                    *reinterpret_cast<uint32_t*>(
                        smem + SM_A + (uint32_t)lr * LDAB + (uint32_t)col * 2) =
                        pack_h2(y0, y1);
                }
            }
        __syncthreads();              // A rewrite complete
    }

    // ---- Heads: 4 accumulate passes over B1/B0 ----
    float cm[2][4][4], cs[2][4][4];
    zero_c(cm); zero_c(cs);

    CP_WAIT(1);                       // WmHi ready
    __syncthreads();
    mma_accum(a_base, WB[1], cm);     // cm += A * Wm_hi
    __syncthreads();
    copy_w_async(WDST[1], W_HI(7), t);   // WsHi -> B1

    CP_WAIT(1);                       // WmLo ready
    __syncthreads();
    mma_accum(a_base, WB[0], cm);     // cm += A * Wm_lo
    __syncthreads();
    copy_w_async(WDST[0], W_LO(7), t);   // WsLo -> B0

    CP_WAIT(1);                       // WsHi ready
    __syncthreads();
    mma_accum(a_base, WB[1], cs);     // cs += A * Ws_hi

    CP_WAIT(0);                       // WsLo ready
    __syncthreads();
    mma_accum(a_base, WB[0], cs);     // cs += A * Ws_lo

    // ---- Fused epilogue: mu, std, z ----
#pragma unroll
    for (int mt = 0; mt < 2; mt++)
#pragma unroll
        for (int half = 0; half < 2; half++) {
            int row = row0 + rloc + mt * 16 + half * 8;
            if (row < n) {
#pragma unroll
                for (int nt = 0; nt < 4; nt++) {
                    int col = cbase + nt * 8;
                    float2 bbm = *reinterpret_cast<const float2*>(bm + col);
                    float2 bbs = *reinterpret_cast<const float2*>(bs + col);
                    float mu0 = cm[mt][nt][2 * half + 0] + bbm.x;
                    float mu1 = cm[mt][nt][2 * half + 1] + bbm.y;
                    float s0 = softplus5f_(cs[mt][nt][2 * half + 0] + bbs.x);
                    float s1 = softplus5f_(cs[mt][nt][2 * half + 1] + bbs.y);
                    uint32_t i0 = (uint32_t)row * ND + (uint32_t)col;
                    float u0 = tf_uniform(i0);
                    float u1 = tf_uniform(i0 + 1);
                    size_t p = (size_t)row * ND + col;
                    *reinterpret_cast<float2*>(muo + p) = make_float2(mu0, mu1);
                    *reinterpret_cast<float2*>(sto + p) = make_float2(s0, s1);
                    *reinterpret_cast<float2*>(zo + p) =
                        make_float2(fmaf(s0, u0, mu0), fmaf(s1, u1, mu1));
                }
            }
        }
}

// ---------------------------------------------------------------------------
// CSR build: count -> per-block scan -> offsets (block prefix inline) -> fill
// ---------------------------------------------------------------------------
__global__ void cnt_accum_kernel(const int* __restrict__ col, int* cnt, int E) {
    int e = blockIdx.x * blockDim.x + threadIdx.x;
    if (e < E) atomicAdd(&cnt[col[e]], 1);
}

__global__ void scan1_kernel(const int* __restrict__ cnt, int* __restrict__ off,
                             int* __restrict__ bsum, int n) {
    __shared__ int ts[256];
    int t = threadIdx.x;
    int base = blockIdx.x * 1024 + t * 4;
    int v0 = (base + 0 < n) ? cnt[base + 0] : 0;
    int v1 = (base + 1 < n) ? cnt[base + 1] : 0;
    int v2 = (base + 2 < n) ? cnt[base + 2] : 0;
    int v3 = (base + 3 < n) ? cnt[base + 3] : 0;
    ts[t] = v0 + v1 + v2 + v3;
    __syncthreads();
    for (int d = 1; d < 256; d <<= 1) {
        int x = (t >= d) ? ts[t - d] : 0;
        __syncthreads();
        ts[t] += x;
        __syncthreads();
    }
    int run = (t > 0) ? ts[t - 1] : 0;
    if (base + 0 < n) off[base + 0] = run;  run += v0;
    if (base + 1 < n) off[base + 1] = run;  run += v1;
    if (base + 2 < n) off[base + 2] = run;  run += v2;
    if (base + 3 < n) off[base + 3] = run;
    if (t == 255) bsum[blockIdx.x] = ts[255];
}

// Adds inline block-prefix of bsum (<=49 cached loads/thread), writes cur,
// dinv, and off[n] = E. Replaces the old single-thread scan2.
__global__ void scan3_kernel(int* __restrict__ off, int* __restrict__ cur,
                             const int* __restrict__ cnt, const int* __restrict__ bsum,
                             float* __restrict__ dinv, int n, int E) {
    int i = blockIdx.x * blockDim.x + threadIdx.x;
    if (i == 0) off[n] = E;
    if (i >= n) return;
    int blk = i >> 10;
    int pre = 0;
    for (int b = 0; b < blk; b++) pre += bsum[b];
    int o = off[i] + pre;
    off[i] = o;
    cur[i] = o;
    dinv[i] = rsqrtf((float)cnt[i] + 1.0f);
}

__global__ void fill_kernel(const int* __restrict__ row, const int* __restrict__ col,
                            int* __restrict__ cur, int* __restrict__ csr, int E) {
    int e = blockIdx.x * blockDim.x + threadIdx.x;
    if (e >= E) return;
    int pos = atomicAdd(&cur[col[e]], 1);
    csr[pos] = row[e];
}

// ---------------------------------------------------------------------------
// Launcher
// ---------------------------------------------------------------------------
extern "C" void kernel_launch(void* const* d_in, const int* in_sizes, int n_in,
                              void* d_out, int out_size)
{
    const float* x      = (const float*)d_in[0];
    const int*   eidx   = (const int*)  d_in[1];
    const float* gcn_w  = (const float*)d_in[2];
    const float* gcn_b  = (const float*)d_in[3];
    const float* enc_w  = (const float*)d_in[4];
    const float* enc_b  = (const float*)d_in[5];
    const float* mean_w = (const float*)d_in[6];
    const float* mean_b = (const float*)d_in[7];
    const float* std_w  = (const float*)d_in[8];
    const float* std_b  = (const float*)d_in[9];
    float* out = (float*)d_out;

    const int n  = in_sizes[0] / ND;          // 50000
    const int E  = in_sizes[1] / 2;           // 800000
    const int NE = n * ND;

    __half *h0, *ws;
    float *dinv;
    int *cnt, *off, *cur, *csr, *bsum;
    cudaGetSymbolAddress((void**)&h0,   g_h0);
    cudaGetSymbolAddress((void**)&dinv, g_dinv);
    cudaGetSymbolAddress((void**)&cnt,  g_cnt);
    cudaGetSymbolAddress((void**)&off,  g_off);
    cudaGetSymbolAddress((void**)&cur,  g_cur);
    cudaGetSymbolAddress((void**)&csr,  g_csr);
    cudaGetSymbolAddress((void**)&bsum, g_bsum);
    cudaGetSymbolAddress((void**)&ws,   g_wsplit);

    cudaFuncSetAttribute(gemm_f32in, cudaFuncAttributeMaxDynamicSharedMemorySize, SMEM_G);
    cudaFuncSetAttribute(mega,       cudaFuncAttributeMaxDynamicSharedMemorySize, SMEM_G);

    const int gblocks = (n + 63) / 64;        // 782
    const int nblk = (n + 1023) / 1024;

#define WLHI(l) (ws + (size_t)(l) * 2 * MAT_ELEMS)

    // Fork: CSR build on side stream, overlapping wprep + GEMM0.
    cudaStream_t s2;
    cudaStreamCreateWithFlags(&s2, cudaStreamNonBlocking);
    cudaEvent_t ev1, ev2;
    cudaEventCreateWithFlags(&ev1, cudaEventDisableTiming);
    cudaEventCreateWithFlags(&ev2, cudaEventDisableTiming);

    cudaEventRecord(ev1, 0);
    cudaStreamWaitEvent(s2, ev1, 0);
    cudaMemsetAsync(cnt, 0, n * sizeof(int), s2);
    cnt_accum_kernel<<<(E + 255) / 256, 256, 0, s2>>>(eidx + E, cnt, E);
    scan1_kernel<<<nblk, 256, 0, s2>>>(cnt, off, bsum, n);
    scan3_kernel<<<(n + 255) / 256, 256, 0, s2>>>(off, cur, cnt, bsum, dinv, n, E);
    fill_kernel<<<(E + 255) / 256, 256, 0, s2>>>(eidx, eidx + E, cur, csr, E);
    cudaEventRecord(ev2, s2);

    // Main stream: weight prep + GEMM0 concurrently with CSR build.
    {
        dim3 grid(ND * ND / 256, NLAYER);
        wprep_kernel<<<grid, 256>>>(gcn_w, enc_w, mean_w, std_w, ws);
    }
    gemm_f32in<<<gblocks, 256, SMEM_G>>>(x, WLHI(0), h0, n);

    // Join, then fused gather + 5 layers + heads + z in one launch.
    cudaStreamWaitEvent(0, ev2, 0);
    mega<<<gblocks, 256, SMEM_G>>>(h0, dinv, off, csr, gcn_b,
                                   ws, enc_b, mean_b, std_b,
                                   out, out + NE, out + 2 * NE, n);

    cudaEventDestroy(ev1);
    cudaEventDestroy(ev2);
    cudaStreamDestroy(s2);
}

// round 14
// speedup vs baseline: 1.1443x; 1.1443x over previous
#include <cuda_runtime.h>
#include <cuda_fp16.h>
#include <cstdint>

#define ND 128
static const int MAXN = 50000;
static const int MAXE = 800000;

#define LDA 136                       // padded row length (fp16 elems)
#define LDAB (LDA * 2)                // 272 bytes per row
#define MAT_ELEMS (128 * LDA)         // 17408
#define MAT_BYTES (MAT_ELEMS * 2)     // 34816
#define NLAYER 8

// Scratch (device globals; allocation-free rule). Activations fp16.
__device__ __align__(16) __half g_h0[MAXN * ND];
__device__ __align__(16) __half g_h1[MAXN * ND];
__device__ float g_dinv[MAXN];
__device__ int   g_cnt[MAXN];
__device__ int   g_off[MAXN + 1];
__device__ int   g_cur[MAXN];
__device__ int   g_csr[MAXE];
__device__ int   g_bsum[128];
__device__ __align__(16) __half g_wsplit[NLAYER * 2 * MAT_ELEMS];

// ---------------------------------------------------------------------------
// Helpers
// ---------------------------------------------------------------------------
__device__ __forceinline__ uint32_t smem_u32(const void* p) {
    uint32_t a;
    asm("{ .reg .u64 t; cvta.to.shared.u64 t, %1; cvt.u32.u64 %0, t; }"
        : "=r"(a) : "l"(p));
    return a;
}

__device__ __forceinline__ void ldsm_x4(uint32_t& r0, uint32_t& r1,
                                        uint32_t& r2, uint32_t& r3, uint32_t addr) {
    asm volatile("ldmatrix.sync.aligned.m8n8.x4.shared.b16 {%0,%1,%2,%3}, [%4];"
                 : "=r"(r0), "=r"(r1), "=r"(r2), "=r"(r3) : "r"(addr));
}

__device__ __forceinline__ void mma16816(float& c0, float& c1, float& c2, float& c3,
                                         uint32_t a0, uint32_t a1, uint32_t a2, uint32_t a3,
                                         uint32_t b0, uint32_t b1) {
    asm volatile(
        "mma.sync.aligned.m16n8k16.row.col.f32.f16.f16.f32 "
        "{%0,%1,%2,%3}, {%4,%5,%6,%7}, {%8,%9}, {%0,%1,%2,%3};"
        : "+f"(c0), "+f"(c1), "+f"(c2), "+f"(c3)
        : "r"(a0), "r"(a1), "r"(a2), "r"(a3), "r"(b0), "r"(b1));
}

__device__ __forceinline__ uint32_t pack_h2(float a, float b) {
    __half ha = __float2half_rn(a), hb = __float2half_rn(b);
    return (uint32_t)__half_as_ushort(ha) |
           ((uint32_t)__half_as_ushort(hb) << 16);
}

__device__ __forceinline__ float sigmoidf_(float y) {
    return __fdividef(1.0f, 1.0f + __expf(-y));
}
__device__ __forceinline__ float softplus5f_(float y) {
    float t = y - 5.0f;
    return fmaxf(t, 0.0f) + log1pf(__expf(-fabsf(t)));
}

// ---------------------------------------------------------------------------
// W prep: per layer l, W^T split into fp16 hi/lo, padded ldmatrix layout.
// Layers: 0=gcn, 1..5=enc[i], 6=mean, 7=std. (lo used only by heads)
// ---------------------------------------------------------------------------
__global__ void wprep_kernel(const float* __restrict__ gcn,
                             const float* __restrict__ enc,
                             const float* __restrict__ meanw,
                             const float* __restrict__ stdw,
                             __half* __restrict__ dst)
{
    int l = blockIdx.y;
    const float* W = (l == 0) ? gcn
                   : (l <= 5) ? enc + (l - 1) * ND * ND
                   : (l == 6) ? meanw : stdw;
    int i = blockIdx.x * blockDim.x + threadIdx.x;
    int nn = i >> 7, k = i & 127;
    float w = W[k * ND + nn];
    __half hi = __float2half_rn(w);
    __half lo = __float2half_rn(w - __half2float(hi));
    __half* base = dst + (size_t)l * 2 * MAT_ELEMS;
    base[nn * LDA + k] = hi;
    base[MAT_ELEMS + nn * LDA + k] = lo;
}

// ---------------------------------------------------------------------------
// MMA body, warp tile 32x32 (accumulating).
// ---------------------------------------------------------------------------
__device__ __forceinline__ void mma_accum(uint32_t a_base, uint32_t Bb,
                                          float c[2][4][4])
{
#pragma unroll
    for (int ks = 0; ks < 8; ks++) {
        const uint32_t kb = (uint32_t)(ks * 16) * 2;
        uint32_t a[2][4];
#pragma unroll
        for (int mt = 0; mt < 2; mt++)
            ldsm_x4(a[mt][0], a[mt][1], a[mt][2], a[mt][3],
                    a_base + (uint32_t)(mt * 16) * LDAB + kb);
        uint32_t b[2][4];
#pragma unroll
        for (int q = 0; q < 2; q++)
            ldsm_x4(b[q][0], b[q][1], b[q][2], b[q][3],
                    Bb + (uint32_t)(q * 16) * LDAB + kb);
#pragma unroll
        for (int mt = 0; mt < 2; mt++)
#pragma unroll
            for (int nt = 0; nt < 4; nt++) {
                uint32_t b0 = b[nt >> 1][nt & 1];
                uint32_t b1 = b[nt >> 1][(nt & 1) + 2];
                mma16816(c[mt][nt][0], c[mt][nt][1], c[mt][nt][2], c[mt][nt][3],
                         a[mt][0], a[mt][1], a[mt][2], a[mt][3], b0, b1);
            }
    }
}

__device__ __forceinline__ void zero_c(float c[2][4][4]) {
#pragma unroll
    for (int mt = 0; mt < 2; mt++)
#pragma unroll
        for (int nt = 0; nt < 4; nt++)
#pragma unroll
            for (int i = 0; i < 4; i++) c[mt][nt][i] = 0.0f;
}

// ---------------------------------------------------------------------------
// Layout: CTA 64x128, 256 threads, 8 warps (2m x 4n), warp tile 32x32.
// mega smem: A[64][136] (17408) + W buf0 (34816) + W buf1 (34816) = 87040 B
// -> 2 CTAs/SM.
// ---------------------------------------------------------------------------
#define SM_A 0
#define SM_W0 17408
#define SM_W1 52224
#define SMEM_G 87040

// Sync copy of one hi matrix (2176 uint4) -- used by gemm_f32in.
__device__ __forceinline__ void copy_w_hi(char* smem, uint32_t dst_off,
                                          const __half* src, int t) {
    const uint4* s = reinterpret_cast<const uint4*>(src);
    uint4* d = reinterpret_cast<uint4*>(smem + dst_off);
#pragma unroll
    for (int i = 0; i < 8; i++) d[t + 256 * i] = s[t + 256 * i];
    if (t < 128) d[t + 2048] = s[t + 2048];
}

// Async copy of one hi matrix (2176 uint4) + commit group.
__device__ __forceinline__ void copy_w_async(uint32_t dst, const __half* src, int t) {
#pragma unroll
    for (int i = 0; i < 8; i++) {
        asm volatile("cp.async.cg.shared.global [%0], [%1], 16;"
                     :: "r"(dst + (uint32_t)(t + 256 * i) * 16),
                        "l"(src + (size_t)(t + 256 * i) * 8) : "memory");
    }
    if (t < 128) {
        asm volatile("cp.async.cg.shared.global [%0], [%1], 16;"
                     :: "r"(dst + (uint32_t)(t + 2048) * 16),
                        "l"(src + (size_t)(t + 2048) * 8) : "memory");
    }
    asm volatile("cp.async.commit_group;" ::: "memory");
}

#define CP_WAIT(N) asm volatile("cp.async.wait_group %0;" :: "n"(N) : "memory")

// ---- Layer 0: fp32 X -> fp16 Y (1-term, no bias/act) ----
__global__ void __launch_bounds__(256, 2)
gemm_f32in(const float* __restrict__ X, const __half* __restrict__ Bpre,
           __half* __restrict__ Y, int n)
{
    extern __shared__ char smem[];
    const uint32_t sb = smem_u32(smem);
    const int t = threadIdx.x;
    const int lane = t & 31, wid = t >> 5;
    const int warp_m = wid >> 2, warp_n = wid & 3;
    const int row0 = blockIdx.x * 64;

    copy_w_hi(smem, SM_W0, Bpre, t);
    {
        const float4* Xg = reinterpret_cast<const float4*>(X + (size_t)row0 * ND);
#pragma unroll
        for (int it = 0; it < 8; it++) {
            int idx = t + it * 256;
            int row = idx >> 5, kq = idx & 31;
            float4 v = make_float4(0.f, 0.f, 0.f, 0.f);
            if (row0 + row < n) v = Xg[(size_t)row * 32 + kq];
            uint32_t o = (uint32_t)row * LDAB + (uint32_t)kq * 8;
            *reinterpret_cast<uint2*>(smem + SM_A + o) =
                make_uint2(pack_h2(v.x, v.y), pack_h2(v.z, v.w));
        }
    }
    __syncthreads();

    const uint32_t lrow = (uint32_t)(lane & 15);
    const uint32_t lk = (uint32_t)((lane >> 4) * 8) * 2;
    const uint32_t a_base = sb + SM_A + ((uint32_t)(warp_m * 32) + lrow) * LDAB + lk;
    const uint32_t b_off = ((uint32_t)(warp_n * 32) + lrow) * LDAB + lk;

    float c[2][4][4];
    zero_c(c);
    mma_accum(a_base, sb + SM_W0 + b_off, c);

    const int rbase = row0 + warp_m * 32 + (lane >> 2);
    const int cbase = warp_n * 32 + (lane & 3) * 2;
#pragma unroll
    for (int mt = 0; mt < 2; mt++)
#pragma unroll
        for (int half = 0; half < 2; half++) {
            int row = rbase + mt * 16 + half * 8;
            if (row < n) {
#pragma unroll
                for (int nt = 0; nt < 4; nt++) {
                    int col = cbase + nt * 8;
                    *reinterpret_cast<uint32_t*>(Y + (size_t)row * ND + col) =
                        pack_h2(c[mt][nt][2 * half + 0], c[mt][nt][2 * half + 1]);
                }
            }
        }
}

// ---------------------------------------------------------------------------
// Threefry-2x32 (JAX partitionable), key = (0, 42)
// ---------------------------------------------------------------------------
__device__ __forceinline__ uint32_t rotl32(uint32_t x, int r) {
    return (x << r) | (x >> (32 - r));
}

__device__ __forceinline__ float tf_uniform(uint32_t i) {
    uint32_t x0 = 0u, x1 = i;
    const uint32_t k0 = 0u, k1 = 42u, k2 = 0u ^ 42u ^ 0x1BD11BDAu;
    x0 += k0; x1 += k1;
#define TF_ROUND(r) { x0 += x1; x1 = rotl32(x1, r); x1 ^= x0; }
    TF_ROUND(13) TF_ROUND(15) TF_ROUND(26) TF_ROUND(6)
    x0 += k1; x1 += k2 + 1u;
    TF_ROUND(17) TF_ROUND(29) TF_ROUND(16) TF_ROUND(24)
    x0 += k2; x1 += k0 + 2u;
    TF_ROUND(13) TF_ROUND(15) TF_ROUND(26) TF_ROUND(6)
    x0 += k0; x1 += k1 + 3u;
    TF_ROUND(17) TF_ROUND(29) TF_ROUND(16) TF_ROUND(24)
    x0 += k1; x1 += k2 + 4u;
    TF_ROUND(13) TF_ROUND(15) TF_ROUND(26) TF_ROUND(6)
    x0 += k2; x1 += k0 + 5u;
#undef TF_ROUND
    uint32_t bits = x0 ^ x1;
    return __uint_as_float((bits >> 9) | 0x3f800000u) - 1.0f;
}

// ---------------------------------------------------------------------------
// Megakernel @ 2 CTAs/SM with cp.async double-buffered weights (R11 form):
// h1 -> 5 sigmoid layers (1-term, in-place A) -> heads (2-term over 4
// accumulate passes) -> fused z epilogue.
// ---------------------------------------------------------------------------
__global__ void __launch_bounds__(256, 2)
mega(const __half* __restrict__ H1, const __half* __restrict__ ws,
     const float* __restrict__ enc_b,
     const float* __restrict__ bm, const float* __restrict__ bs,
     float* __restrict__ zo, float* __restrict__ muo, float* __restrict__ sto,
     int n)
{
    extern __shared__ char smem[];
    const uint32_t sb = smem_u32(smem);
    const int t = threadIdx.x;
    const int lane = t & 31, wid = t >> 5;
    const int warp_m = wid >> 2, warp_n = wid & 3;
    const int row0 = blockIdx.x * 64;

#define W_HI(l) (ws + (size_t)(l) * 2 * MAT_ELEMS)
#define W_LO(l) (ws + (size_t)(l) * 2 * MAT_ELEMS + MAT_ELEMS)

    // Prologue: prefetch W1 -> B0, W2 -> B1 (two groups), load A tile.
    copy_w_async(sb + SM_W0, W_HI(1), t);
    copy_w_async(sb + SM_W1, W_HI(2), t);
    {
        const uint4* src = reinterpret_cast<const uint4*>(H1);
#pragma unroll
        for (int i = 0; i < 4; i++) {
            int idx = t + 256 * i;
            int row = idx >> 4, q = idx & 15;
            uint4 v = make_uint4(0u, 0u, 0u, 0u);
            if (row0 + row < n) v = src[(size_t)(row0 + row) * 16 + q];
            *reinterpret_cast<uint4*>(smem + SM_A + (uint32_t)row * LDAB + q * 16) = v;
        }
    }

    const uint32_t lrow = (uint32_t)(lane & 15);
    const uint32_t lk = (uint32_t)((lane >> 4) * 8) * 2;
    const uint32_t a_base = sb + SM_A + ((uint32_t)(warp_m * 32) + lrow) * LDAB + lk;
    const uint32_t b_off = ((uint32_t)(warp_n * 32) + lrow) * LDAB + lk;
    const uint32_t WB[2] = {sb + SM_W0 + b_off, sb + SM_W1 + b_off};
    const uint32_t WDST[2] = {sb + SM_W0, sb + SM_W1};

    const int rloc = warp_m * 32 + (lane >> 2);
    const int cbase = warp_n * 32 + (lane & 3) * 2;

    // Prefetch order after the prologue, issued into the just-freed buffer:
    // j=0:W3, j=1:W4, j=2:W5, j=3:WmHi, j=4:WmLo; heads: WsHi, WsLo.
    const __half* nextW[5] = {W_HI(3), W_HI(4), W_HI(5), W_HI(6), W_LO(6)};

    // ---- 5 encoder layers ----
    for (int j = 0; j < 5; j++) {
        CP_WAIT(1);                   // current buffer's copy complete
        __syncthreads();              // visible to all warps; A ready (j=0)

        float c[2][4][4];
        zero_c(c);
        mma_accum(a_base, WB[j & 1], c);
        __syncthreads();              // all reads of A and W[j&1] done

        // Refill freed buffer; epilogue in parallel with the async copy.
        copy_w_async(WDST[j & 1], nextW[j], t);

        const float* bl = enc_b + j * ND;
#pragma unroll
        for (int mt = 0; mt < 2; mt++)
#pragma unroll
            for (int half = 0; half < 2; half++) {
                int lr = rloc + mt * 16 + half * 8;
#pragma unroll
                for (int nt = 0; nt < 4; nt++) {
                    int col = cbase + nt * 8;
                    float2 bb = *reinterpret_cast<const float2*>(bl + col);
                    float y0 = sigmoidf_(c[mt][nt][2 * half + 0] + bb.x);
                    float y1 = sigmoidf_(c[mt][nt][2 * half + 1] + bb.y);
                    *reinterpret_cast<uint32_t*>(
                        smem + SM_A + (uint32_t)lr * LDAB + (uint32_t)col * 2) =
                        pack_h2(y0, y1);
                }
            }
        __syncthreads();              // A rewrite complete
    }

    // ---- Heads: 4 accumulate passes over B1/B0 ----
    float cm[2][4][4], cs[2][4][4];
    zero_c(cm); zero_c(cs);

    CP_WAIT(1);                       // WmHi ready
    __syncthreads();
    mma_accum(a_base, WB[1], cm);     // cm += A * Wm_hi
    __syncthreads();
    copy_w_async(WDST[1], W_HI(7), t);   // WsHi -> B1

    CP_WAIT(1);                       // WmLo ready
    __syncthreads();
    mma_accum(a_base, WB[0], cm);     // cm += A * Wm_lo
    __syncthreads();
    copy_w_async(WDST[0], W_LO(7), t);   // WsLo -> B0

    CP_WAIT(1);                       // WsHi ready
    __syncthreads();
    mma_accum(a_base, WB[1], cs);     // cs += A * Ws_hi

    CP_WAIT(0);                       // WsLo ready
    __syncthreads();
    mma_accum(a_base, WB[0], cs);     // cs += A * Ws_lo

    // ---- Fused epilogue: mu, std, z ----
#pragma unroll
    for (int mt = 0; mt < 2; mt++)
#pragma unroll
        for (int half = 0; half < 2; half++) {
            int row = row0 + rloc + mt * 16 + half * 8;
            if (row < n) {
#pragma unroll
                for (int nt = 0; nt < 4; nt++) {
                    int col = cbase + nt * 8;
                    float2 bbm = *reinterpret_cast<const float2*>(bm + col);
                    float2 bbs = *reinterpret_cast<const float2*>(bs + col);
                    float mu0 = cm[mt][nt][2 * half + 0] + bbm.x;
                    float mu1 = cm[mt][nt][2 * half + 1] + bbm.y;
                    float s0 = softplus5f_(cs[mt][nt][2 * half + 0] + bbs.x);
                    float s1 = softplus5f_(cs[mt][nt][2 * half + 1] + bbs.y);
                    uint32_t i0 = (uint32_t)row * ND + (uint32_t)col;
                    float u0 = tf_uniform(i0);
                    float u1 = tf_uniform(i0 + 1);
                    size_t p = (size_t)row * ND + col;
                    *reinterpret_cast<float2*>(muo + p) = make_float2(mu0, mu1);
                    *reinterpret_cast<float2*>(sto + p) = make_float2(s0, s1);
                    *reinterpret_cast<float2*>(zo + p) =
                        make_float2(fmaf(s0, u0, mu0), fmaf(s1, u1, mu1));
                }
            }
        }
}

// ---------------------------------------------------------------------------
// GCN aggregation: CSR build + warp-per-node gather (fp16 h0 -> fp16 h1)
// ---------------------------------------------------------------------------
__global__ void cnt_accum_kernel(const int* __restrict__ col, int* cnt, int E) {
    int e = blockIdx.x * blockDim.x + threadIdx.x;
    if (e < E) atomicAdd(&cnt[col[e]], 1);
}

__global__ void scan1_kernel(const int* __restrict__ cnt, int* __restrict__ off,
                             int* __restrict__ bsum, int n) {
    __shared__ int ts[256];
    int t = threadIdx.x;
    int base = blockIdx.x * 1024 + t * 4;
    int v0 = (base + 0 < n) ? cnt[base + 0] : 0;
    int v1 = (base + 1 < n) ? cnt[base + 1] : 0;
    int v2 = (base + 2 < n) ? cnt[base + 2] : 0;
    int v3 = (base + 3 < n) ? cnt[base + 3] : 0;
    ts[t] = v0 + v1 + v2 + v3;
    __syncthreads();
    for (int d = 1; d < 256; d <<= 1) {
        int x = (t >= d) ? ts[t - d] : 0;
        __syncthreads();
        ts[t] += x;
        __syncthreads();
    }
    int run = (t > 0) ? ts[t - 1] : 0;
    if (base + 0 < n) off[base + 0] = run;  run += v0;
    if (base + 1 < n) off[base + 1] = run;  run += v1;
    if (base + 2 < n) off[base + 2] = run;  run += v2;
    if (base + 3 < n) off[base + 3] = run;
    if (t == 255) bsum[blockIdx.x] = ts[255];
}

// Adds inline block-prefix of bsum (<=49 cached loads/thread), writes cur,
// dinv, and off[n] = E. Replaces the old single-thread scan2.
__global__ void scan3_kernel(int* __restrict__ off, int* __restrict__ cur,
                             const int* __restrict__ cnt, const int* __restrict__ bsum,
                             float* __restrict__ dinv, int n, int E) {
    int i = blockIdx.x * blockDim.x + threadIdx.x;
    if (i == 0) off[n] = E;
    if (i >= n) return;
    int blk = i >> 10;
    int pre = 0;
    for (int b = 0; b < blk; b++) pre += bsum[b];
    int o = off[i] + pre;
    off[i] = o;
    cur[i] = o;
    dinv[i] = rsqrtf((float)cnt[i] + 1.0f);
}

__global__ void fill_kernel(const int* __restrict__ row, const int* __restrict__ col,
                            int* __restrict__ cur, int* __restrict__ csr, int E) {
    int e = blockIdx.x * blockDim.x + threadIdx.x;
    if (e >= E) return;
    int pos = atomicAdd(&cur[col[e]], 1);
    csr[pos] = row[e];
}

// Warp per node, fp16 rows: lane covers 4 cols (uint2 = 4 halves).
__global__ void gather_kernel(const __half* __restrict__ h0,
                              const float* __restrict__ dinv,
                              const int* __restrict__ off,
                              const int* __restrict__ csr,
                              const float* __restrict__ b,
                              __half* __restrict__ h1, int n)
{
    int w = (blockIdx.x * blockDim.x + threadIdx.x) >> 5;
    int lane = threadIdx.x & 31;
    if (w >= n) return;
    float di = dinv[w];
    const uint2* H0 = reinterpret_cast<const uint2*>(h0);   // 32 uint2 per row

    uint2 sv = H0[(size_t)w * 32 + lane];
    float2 s0 = __half22float2(*reinterpret_cast<__half2*>(&sv.x));
    float2 s1 = __half22float2(*reinterpret_cast<__half2*>(&sv.y));
    float dii = di * di;
    float a0 = s0.x * dii, a1 = s0.y * dii, a2 = s1.x * dii, a3 = s1.y * dii;

    int j = off[w], end = off[w + 1];
    for (; j + 3 < end; j += 4) {
        int r0 = csr[j], r1 = csr[j + 1], r2 = csr[j + 2], r3 = csr[j + 3];
        float n0 = dinv[r0] * di, n1 = dinv[r1] * di;
        float n2 = dinv[r2] * di, n3 = dinv[r3] * di;
        uint2 v0 = H0[(size_t)r0 * 32 + lane];
        uint2 v1 = H0[(size_t)r1 * 32 + lane];
        uint2 v2 = H0[(size_t)r2 * 32 + lane];
        uint2 v3 = H0[(size_t)r3 * 32 + lane];
        float2 p, q;
        p = __half22float2(*reinterpret_cast<__half2*>(&v0.x));
        q = __half22float2(*reinterpret_cast<__half2*>(&v0.y));
        a0 += n0 * p.x; a1 += n0 * p.y; a2 += n0 * q.x; a3 += n0 * q.y;
        p = __half22float2(*reinterpret_cast<__half2*>(&v1.x));
        q = __half22float2(*reinterpret_cast<__half2*>(&v1.y));
        a0 += n1 * p.x; a1 += n1 * p.y; a2 += n1 * q.x; a3 += n1 * q.y;
        p = __half22float2(*reinterpret_cast<__half2*>(&v2.x));
        q = __half22float2(*reinterpret_cast<__half2*>(&v2.y));
        a0 += n2 * p.x; a1 += n2 * p.y; a2 += n2 * q.x; a3 += n2 * q.y;
        p = __half22float2(*reinterpret_cast<__half2*>(&v3.x));
        q = __half22float2(*reinterpret_cast<__half2*>(&v3.y));
        a0 += n3 * p.x; a1 += n3 * p.y; a2 += n3 * q.x; a3 += n3 * q.y;
    }
    for (; j < end; j++) {
        int r = csr[j];
        float nr = dinv[r] * di;
        uint2 v = H0[(size_t)r * 32 + lane];
        float2 p = __half22float2(*reinterpret_cast<__half2*>(&v.x));
        float2 q = __half22float2(*reinterpret_cast<__half2*>(&v.y));
        a0 += nr * p.x; a1 += nr * p.y; a2 += nr * q.x; a3 += nr * q.y;
    }
    float4 bb = reinterpret_cast<const float4*>(b)[lane];
    uint2 outv;
    outv.x = pack_h2(a0 + bb.x, a1 + bb.y);
    outv.y = pack_h2(a2 + bb.z, a3 + bb.w);
    reinterpret_cast<uint2*>(h1)[(size_t)w * 32 + lane] = outv;
}

// ---------------------------------------------------------------------------
// Launcher
// ---------------------------------------------------------------------------
extern "C" void kernel_launch(void* const* d_in, const int* in_sizes, int n_in,
                              void* d_out, int out_size)
{
    const float* x      = (const float*)d_in[0];
    const int*   eidx   = (const int*)  d_in[1];
    const float* gcn_w  = (const float*)d_in[2];
    const float* gcn_b  = (const float*)d_in[3];
    const float* enc_w  = (const float*)d_in[4];
    const float* enc_b  = (const float*)d_in[5];
    const float* mean_w = (const float*)d_in[6];
    const float* mean_b = (const float*)d_in[7];
    const float* std_w  = (const float*)d_in[8];
    const float* std_b  = (const float*)d_in[9];
    float* out = (float*)d_out;

    const int n  = in_sizes[0] / ND;          // 50000
    const int E  = in_sizes[1] / 2;           // 800000
    const int NE = n * ND;

    __half *h0, *h1, *ws;
    float *dinv;
    int *cnt, *off, *cur, *csr, *bsum;
    cudaGetSymbolAddress((void**)&h0,   g_h0);
    cudaGetSymbolAddress((void**)&h1,   g_h1);
    cudaGetSymbolAddress((void**)&dinv, g_dinv);
    cudaGetSymbolAddress((void**)&cnt,  g_cnt);
    cudaGetSymbolAddress((void**)&off,  g_off);
    cudaGetSymbolAddress((void**)&cur,  g_cur);
    cudaGetSymbolAddress((void**)&csr,  g_csr);
    cudaGetSymbolAddress((void**)&bsum, g_bsum);
    cudaGetSymbolAddress((void**)&ws,   g_wsplit);

    cudaFuncSetAttribute(gemm_f32in, cudaFuncAttributeMaxDynamicSharedMemorySize, SMEM_G);
    cudaFuncSetAttribute(mega,       cudaFuncAttributeMaxDynamicSharedMemorySize, SMEM_G);

    const int gblocks = (n + 63) / 64;        // 782
    const int nblk = (n + 1023) / 1024;

#define WLHI(l) (ws + (size_t)(l) * 2 * MAT_ELEMS)

    // Fork: CSR build on side stream, overlapping wprep + GEMM0.
    cudaStream_t s2;
    cudaStreamCreateWithFlags(&s2, cudaStreamNonBlocking);
    cudaEvent_t ev1, ev2;
    cudaEventCreateWithFlags(&ev1, cudaEventDisableTiming);
    cudaEventCreateWithFlags(&ev2, cudaEventDisableTiming);

    cudaEventRecord(ev1, 0);
    cudaStreamWaitEvent(s2, ev1, 0);
    cudaMemsetAsync(cnt, 0, n * sizeof(int), s2);
    cnt_accum_kernel<<<(E + 255) / 256, 256, 0, s2>>>(eidx + E, cnt, E);
    scan1_kernel<<<nblk, 256, 0, s2>>>(cnt, off, bsum, n);
    scan3_kernel<<<(n + 255) / 256, 256, 0, s2>>>(off, cur, cnt, bsum, dinv, n, E);
    fill_kernel<<<(E + 255) / 256, 256, 0, s2>>>(eidx, eidx + E, cur, csr, E);
    cudaEventRecord(ev2, s2);

    // Main stream: weight prep + GEMM0 concurrently with CSR build.
    {
        dim3 grid(ND * ND / 256, NLAYER);
        wprep_kernel<<<grid, 256>>>(gcn_w, enc_w, mean_w, std_w, ws);
    }
    gemm_f32in<<<gblocks, 256, SMEM_G>>>(x, WLHI(0), h0, n);

    // Join, then gather (h0 -> h1, + gcn_b).
    cudaStreamWaitEvent(0, ev2, 0);
    gather_kernel<<<(n * 32 + 255) / 256, 256>>>(h0, dinv, off, csr, gcn_b, h1, n);

    // Fused: 5 encoder layers + heads + z, one launch @ 2 CTAs/SM.
    mega<<<gblocks, 256, SMEM_G>>>(h1, ws, enc_b, mean_b, std_b,
                                   out, out + NE, out + 2 * NE, n);

    cudaEventDestroy(ev1);
    cudaEventDestroy(ev2);
    cudaStreamDestroy(s2);
}

// round 15
// speedup vs baseline: 1.2340x; 1.0784x over previous
#include <cuda_runtime.h>
#include <cuda_fp16.h>
#include <cstdint>

#define ND 128
static const int MAXN = 50000;
static const int MAXE = 800000;

#define LDA 136                       // padded row length (fp16 elems)
#define LDAB (LDA * 2)                // 272 bytes per row
#define MAT_ELEMS (128 * LDA)         // 17408
#define MAT_BYTES (MAT_ELEMS * 2)     // 34816
#define NLAYER 8

// Scratch (device globals; allocation-free rule). Activations fp16.
__device__ __align__(16) __half g_h0[MAXN * ND];
__device__ __align__(16) __half g_h1[MAXN * ND];
__device__ float g_dinv[MAXN];
__device__ int   g_cnt[MAXN];
__device__ int   g_off[MAXN + 1];
__device__ int   g_cur[MAXN];
__device__ int   g_csr[MAXE];
__device__ int   g_bsum[128];
__device__ __align__(16) __half g_wsplit[NLAYER * 2 * MAT_ELEMS];

// ---------------------------------------------------------------------------
// Helpers
// ---------------------------------------------------------------------------
__device__ __forceinline__ uint32_t smem_u32(const void* p) {
    uint32_t a;
    asm("{ .reg .u64 t; cvta.to.shared.u64 t, %1; cvt.u32.u64 %0, t; }"
        : "=r"(a) : "l"(p));
    return a;
}

__device__ __forceinline__ void ldsm_x4(uint32_t& r0, uint32_t& r1,
                                        uint32_t& r2, uint32_t& r3, uint32_t addr) {
    asm volatile("ldmatrix.sync.aligned.m8n8.x4.shared.b16 {%0,%1,%2,%3}, [%4];"
                 : "=r"(r0), "=r"(r1), "=r"(r2), "=r"(r3) : "r"(addr));
}

__device__ __forceinline__ void mma16816(float& c0, float& c1, float& c2, float& c3,
                                         uint32_t a0, uint32_t a1, uint32_t a2, uint32_t a3,
                                         uint32_t b0, uint32_t b1) {
    asm volatile(
        "mma.sync.aligned.m16n8k16.row.col.f32.f16.f16.f32 "
        "{%0,%1,%2,%3}, {%4,%5,%6,%7}, {%8,%9}, {%0,%1,%2,%3};"
        : "+f"(c0), "+f"(c1), "+f"(c2), "+f"(c3)
        : "r"(a0), "r"(a1), "r"(a2), "r"(a3), "r"(b0), "r"(b1));
}

__device__ __forceinline__ uint32_t pack_h2(float a, float b) {
    __half ha = __float2half_rn(a), hb = __float2half_rn(b);
    return (uint32_t)__half_as_ushort(ha) |
           ((uint32_t)__half_as_ushort(hb) << 16);
}

__device__ __forceinline__ float sigmoidf_(float y) {
    return __fdividef(1.0f, 1.0f + __expf(-y));
}
__device__ __forceinline__ float softplus5f_(float y) {
    float t = y - 5.0f;
    return fmaxf(t, 0.0f) + log1pf(__expf(-fabsf(t)));
}

// ---------------------------------------------------------------------------
// W prep: per layer l, W^T (fp16 hi) into padded ldmatrix layout.
// Layout keeps the 2*MAT_ELEMS stride per layer (lo plane now unused).
// Layers: 0=gcn, 1..5=enc[i], 6=mean, 7=std.
// ---------------------------------------------------------------------------
__global__ void wprep_kernel(const float* __restrict__ gcn,
                             const float* __restrict__ enc,
                             const float* __restrict__ meanw,
                             const float* __restrict__ stdw,
                             __half* __restrict__ dst)
{
    int l = blockIdx.y;
    const float* W = (l == 0) ? gcn
                   : (l <= 5) ? enc + (l - 1) * ND * ND
                   : (l == 6) ? meanw : stdw;
    int i = blockIdx.x * blockDim.x + threadIdx.x;
    int nn = i >> 7, k = i & 127;
    float w = W[k * ND + nn];
    __half* base = dst + (size_t)l * 2 * MAT_ELEMS;
    base[nn * LDA + k] = __float2half_rn(w);
}

// ---------------------------------------------------------------------------
// MMA body, warp tile 32x32 (accumulating).
// ---------------------------------------------------------------------------
__device__ __forceinline__ void mma_accum(uint32_t a_base, uint32_t Bb,
                                          float c[2][4][4])
{
#pragma unroll
    for (int ks = 0; ks < 8; ks++) {
        const uint32_t kb = (uint32_t)(ks * 16) * 2;
        uint32_t a[2][4];
#pragma unroll
        for (int mt = 0; mt < 2; mt++)
            ldsm_x4(a[mt][0], a[mt][1], a[mt][2], a[mt][3],
                    a_base + (uint32_t)(mt * 16) * LDAB + kb);
        uint32_t b[2][4];
#pragma unroll
        for (int q = 0; q < 2; q++)
            ldsm_x4(b[q][0], b[q][1], b[q][2], b[q][3],
                    Bb + (uint32_t)(q * 16) * LDAB + kb);
#pragma unroll
        for (int mt = 0; mt < 2; mt++)
#pragma unroll
            for (int nt = 0; nt < 4; nt++) {
                uint32_t b0 = b[nt >> 1][nt & 1];
                uint32_t b1 = b[nt >> 1][(nt & 1) + 2];
                mma16816(c[mt][nt][0], c[mt][nt][1], c[mt][nt][2], c[mt][nt][3],
                         a[mt][0], a[mt][1], a[mt][2], a[mt][3], b0, b1);
            }
    }
}

__device__ __forceinline__ void zero_c(float c[2][4][4]) {
#pragma unroll
    for (int mt = 0; mt < 2; mt++)
#pragma unroll
        for (int nt = 0; nt < 4; nt++)
#pragma unroll
            for (int i = 0; i < 4; i++) c[mt][nt][i] = 0.0f;
}

// ---------------------------------------------------------------------------
// Layout: CTA 64x128, 256 threads, 8 warps (2m x 4n), warp tile 32x32.
// mega smem: A[64][136] (17408) + W buf0 (34816) + W buf1 (34816) = 87040 B
// -> 2 CTAs/SM.
// ---------------------------------------------------------------------------
#define SM_A 0
#define SM_W0 17408
#define SM_W1 52224
#define SMEM_G 87040

// Sync copy of one hi matrix (2176 uint4) -- used by gemm_f32in.
__device__ __forceinline__ void copy_w_hi(char* smem, uint32_t dst_off,
                                          const __half* src, int t) {
    const uint4* s = reinterpret_cast<const uint4*>(src);
    uint4* d = reinterpret_cast<uint4*>(smem + dst_off);
#pragma unroll
    for (int i = 0; i < 8; i++) d[t + 256 * i] = s[t + 256 * i];
    if (t < 128) d[t + 2048] = s[t + 2048];
}

// Async copy of one hi matrix (2176 uint4) + commit group.
__device__ __forceinline__ void copy_w_async(uint32_t dst, const __half* src, int t) {
#pragma unroll
    for (int i = 0; i < 8; i++) {
        asm volatile("cp.async.cg.shared.global [%0], [%1], 16;"
                     :: "r"(dst + (uint32_t)(t + 256 * i) * 16),
                        "l"(src + (size_t)(t + 256 * i) * 8) : "memory");
    }
    if (t < 128) {
        asm volatile("cp.async.cg.shared.global [%0], [%1], 16;"
                     :: "r"(dst + (uint32_t)(t + 2048) * 16),
                        "l"(src + (size_t)(t + 2048) * 8) : "memory");
    }
    asm volatile("cp.async.commit_group;" ::: "memory");
}

#define CP_WAIT(N) asm volatile("cp.async.wait_group %0;" :: "n"(N) : "memory")

// ---- Layer 0: fp32 X -> fp16 Y (1-term, no bias/act) ----
__global__ void __launch_bounds__(256, 2)
gemm_f32in(const float* __restrict__ X, const __half* __restrict__ Bpre,
           __half* __restrict__ Y, int n)
{
    extern __shared__ char smem[];
    const uint32_t sb = smem_u32(smem);
    const int t = threadIdx.x;
    const int lane = t & 31, wid = t >> 5;
    const int warp_m = wid >> 2, warp_n = wid & 3;
    const int row0 = blockIdx.x * 64;

    copy_w_hi(smem, SM_W0, Bpre, t);
    {
        const float4* Xg = reinterpret_cast<const float4*>(X + (size_t)row0 * ND);
#pragma unroll
        for (int it = 0; it < 8; it++) {
            int idx = t + it * 256;
            int row = idx >> 5, kq = idx & 31;
            float4 v = make_float4(0.f, 0.f, 0.f, 0.f);
            if (row0 + row < n) v = Xg[(size_t)row * 32 + kq];
            uint32_t o = (uint32_t)row * LDAB + (uint32_t)kq * 8;
            *reinterpret_cast<uint2*>(smem + SM_A + o) =
                make_uint2(pack_h2(v.x, v.y), pack_h2(v.z, v.w));
        }
    }
    __syncthreads();

    const uint32_t lrow = (uint32_t)(lane & 15);
    const uint32_t lk = (uint32_t)((lane >> 4) * 8) * 2;
    const uint32_t a_base = sb + SM_A + ((uint32_t)(warp_m * 32) + lrow) * LDAB + lk;
    const uint32_t b_off = ((uint32_t)(warp_n * 32) + lrow) * LDAB + lk;

    float c[2][4][4];
    zero_c(c);
    mma_accum(a_base, sb + SM_W0 + b_off, c);

    const int rbase = row0 + warp_m * 32 + (lane >> 2);
    const int cbase = warp_n * 32 + (lane & 3) * 2;
#pragma unroll
    for (int mt = 0; mt < 2; mt++)
#pragma unroll
        for (int half = 0; half < 2; half++) {
            int row = rbase + mt * 16 + half * 8;
            if (row < n) {
#pragma unroll
                for (int nt = 0; nt < 4; nt++) {
                    int col = cbase + nt * 8;
                    *reinterpret_cast<uint32_t*>(Y + (size_t)row * ND + col) =
                        pack_h2(c[mt][nt][2 * half + 0], c[mt][nt][2 * half + 1]);
                }
            }
        }
}

// ---------------------------------------------------------------------------
// Threefry-2x32 (JAX partitionable), key = (0, 42)
// ---------------------------------------------------------------------------
__device__ __forceinline__ uint32_t rotl32(uint32_t x, int r) {
    return (x << r) | (x >> (32 - r));
}

__device__ __forceinline__ float tf_uniform(uint32_t i) {
    uint32_t x0 = 0u, x1 = i;
    const uint32_t k0 = 0u, k1 = 42u, k2 = 0u ^ 42u ^ 0x1BD11BDAu;
    x0 += k0; x1 += k1;
#define TF_ROUND(r) { x0 += x1; x1 = rotl32(x1, r); x1 ^= x0; }
    TF_ROUND(13) TF_ROUND(15) TF_ROUND(26) TF_ROUND(6)
    x0 += k1; x1 += k2 + 1u;
    TF_ROUND(17) TF_ROUND(29) TF_ROUND(16) TF_ROUND(24)
    x0 += k2; x1 += k0 + 2u;
    TF_ROUND(13) TF_ROUND(15) TF_ROUND(26) TF_ROUND(6)
    x0 += k0; x1 += k1 + 3u;
    TF_ROUND(17) TF_ROUND(29) TF_ROUND(16) TF_ROUND(24)
    x0 += k1; x1 += k2 + 4u;
    TF_ROUND(13) TF_ROUND(15) TF_ROUND(26) TF_ROUND(6)
    x0 += k2; x1 += k0 + 5u;
#undef TF_ROUND
    uint32_t bits = x0 ^ x1;
    return __uint_as_float((bits >> 9) | 0x3f800000u) - 1.0f;
}

// ---------------------------------------------------------------------------
// Megakernel @ 2 CTAs/SM with cp.async double-buffered weights:
// h1 -> 5 sigmoid layers (1-term, in-place A) -> heads (1-term each) ->
// fused z epilogue.
// Buffer schedule (B0/B1): prologue W1->B0, W2->B1; layer j consumes B[j&1]
// and refills it with nextW[j] = {W3,W4,W5,Wm,Ws}. After the loop the two
// pending groups are exactly Wm(B1) and Ws(B0) -- heads need no extra copies.
// ---------------------------------------------------------------------------
__global__ void __launch_bounds__(256, 2)
mega(const __half* __restrict__ H1, const __half* __restrict__ ws,
     const float* __restrict__ enc_b,
     const float* __restrict__ bm, const float* __restrict__ bs,
     float* __restrict__ zo, float* __restrict__ muo, float* __restrict__ sto,
     int n)
{
    extern __shared__ char smem[];
    const uint32_t sb = smem_u32(smem);
    const int t = threadIdx.x;
    const int lane = t & 31, wid = t >> 5;
    const int warp_m = wid >> 2, warp_n = wid & 3;
    const int row0 = blockIdx.x * 64;

#define W_HI(l) (ws + (size_t)(l) * 2 * MAT_ELEMS)

    // Prologue: prefetch W1 -> B0, W2 -> B1 (two groups), load A tile.
    copy_w_async(sb + SM_W0, W_HI(1), t);
    copy_w_async(sb + SM_W1, W_HI(2), t);
    {
        const uint4* src = reinterpret_cast<const uint4*>(H1);
#pragma unroll
        for (int i = 0; i < 4; i++) {
            int idx = t + 256 * i;
            int row = idx >> 4, q = idx & 15;
            uint4 v = make_uint4(0u, 0u, 0u, 0u);
            if (row0 + row < n) v = src[(size_t)(row0 + row) * 16 + q];
            *reinterpret_cast<uint4*>(smem + SM_A + (uint32_t)row * LDAB + q * 16) = v;
        }
    }

    const uint32_t lrow = (uint32_t)(lane & 15);
    const uint32_t lk = (uint32_t)((lane >> 4) * 8) * 2;
    const uint32_t a_base = sb + SM_A + ((uint32_t)(warp_m * 32) + lrow) * LDAB + lk;
    const uint32_t b_off = ((uint32_t)(warp_n * 32) + lrow) * LDAB + lk;
    const uint32_t WB[2] = {sb + SM_W0 + b_off, sb + SM_W1 + b_off};
    const uint32_t WDST[2] = {sb + SM_W0, sb + SM_W1};

    const int rloc = warp_m * 32 + (lane >> 2);
    const int cbase = warp_n * 32 + (lane & 3) * 2;

    // Prefetch order after the prologue, issued into the just-freed buffer:
    // j=0:W3, j=1:W4, j=2:W5, j=3:Wm, j=4:Ws.
    const __half* nextW[5] = {W_HI(3), W_HI(4), W_HI(5), W_HI(6), W_HI(7)};

    // ---- 5 encoder layers ----
    for (int j = 0; j < 5; j++) {
        CP_WAIT(1);                   // current buffer's copy complete
        __syncthreads();              // visible to all warps; A ready (j=0)

        float c[2][4][4];
        zero_c(c);
        mma_accum(a_base, WB[j & 1], c);
        __syncthreads();              // all reads of A and W[j&1] done

        // Refill freed buffer; epilogue in parallel with the async copy.
        copy_w_async(WDST[j & 1], nextW[j], t);

        const float* bl = enc_b + j * ND;
#pragma unroll
        for (int mt = 0; mt < 2; mt++)
#pragma unroll
            for (int half = 0; half < 2; half++) {
                int lr = rloc + mt * 16 + half * 8;
#pragma unroll
                for (int nt = 0; nt < 4; nt++) {
                    int col = cbase + nt * 8;
                    float2 bb = *reinterpret_cast<const float2*>(bl + col);
                    float y0 = sigmoidf_(c[mt][nt][2 * half + 0] + bb.x);
                    float y1 = sigmoidf_(c[mt][nt][2 * half + 1] + bb.y);
                    *reinterpret_cast<uint32_t*>(
                        smem + SM_A + (uint32_t)lr * LDAB + (uint32_t)col * 2) =
                        pack_h2(y0, y1);
                }
            }
        __syncthreads();              // A rewrite complete
    }

    // ---- Heads: pending groups are Wm(B1), Ws(B0) ----
    float cm[2][4][4], cs[2][4][4];
    zero_c(cm); zero_c(cs);

    CP_WAIT(1);                       // Wm ready (B1)
    __syncthreads();
    mma_accum(a_base, WB[1], cm);     // cm = A * Wm

    CP_WAIT(0);                       // Ws ready (B0)
    __syncthreads();
    mma_accum(a_base, WB[0], cs);     // cs = A * Ws

    // ---- Fused epilogue: mu, std, z ----
#pragma unroll
    for (int mt = 0; mt < 2; mt++)
#pragma unroll
        for (int half = 0; half < 2; half++) {
            int row = row0 + rloc + mt * 16 + half * 8;
            if (row < n) {
#pragma unroll
                for (int nt = 0; nt < 4; nt++) {
                    int col = cbase + nt * 8;
                    float2 bbm = *reinterpret_cast<const float2*>(bm + col);
                    float2 bbs = *reinterpret_cast<const float2*>(bs + col);
                    float mu0 = cm[mt][nt][2 * half + 0] + bbm.x;
                    float mu1 = cm[mt][nt][2 * half + 1] + bbm.y;
                    float s0 = softplus5f_(cs[mt][nt][2 * half + 0] + bbs.x);
                    float s1 = softplus5f_(cs[mt][nt][2 * half + 1] + bbs.y);
                    uint32_t i0 = (uint32_t)row * ND + (uint32_t)col;
                    float u0 = tf_uniform(i0);
                    float u1 = tf_uniform(i0 + 1);
                    size_t p = (size_t)row * ND + col;
                    *reinterpret_cast<float2*>(muo + p) = make_float2(mu0, mu1);
                    *reinterpret_cast<float2*>(sto + p) = make_float2(s0, s1);
                    *reinterpret_cast<float2*>(zo + p) =
                        make_float2(fmaf(s0, u0, mu0), fmaf(s1, u1, mu1));
                }
            }
        }
}

// ---------------------------------------------------------------------------
// GCN aggregation: CSR build + warp-per-node gather (fp16 h0 -> fp16 h1)
// ---------------------------------------------------------------------------
__global__ void cnt_accum_kernel(const int* __restrict__ col, int* cnt, int E) {
    int e = blockIdx.x * blockDim.x + threadIdx.x;
    if (e < E) atomicAdd(&cnt[col[e]], 1);
}

__global__ void scan1_kernel(const int* __restrict__ cnt, int* __restrict__ off,
                             int* __restrict__ bsum, int n) {
    __shared__ int ts[256];
    int t = threadIdx.x;
    int base = blockIdx.x * 1024 + t * 4;
    int v0 = (base + 0 < n) ? cnt[base + 0] : 0;
    int v1 = (base + 1 < n) ? cnt[base + 1] : 0;
    int v2 = (base + 2 < n) ? cnt[base + 2] : 0;
    int v3 = (base + 3 < n) ? cnt[base + 3] : 0;
    ts[t] = v0 + v1 + v2 + v3;
    __syncthreads();
    for (int d = 1; d < 256; d <<= 1) {
        int x = (t >= d) ? ts[t - d] : 0;
        __syncthreads();
        ts[t] += x;
        __syncthreads();
    }
    int run = (t > 0) ? ts[t - 1] : 0;
    if (base + 0 < n) off[base + 0] = run;  run += v0;
    if (base + 1 < n) off[base + 1] = run;  run += v1;
    if (base + 2 < n) off[base + 2] = run;  run += v2;
    if (base + 3 < n) off[base + 3] = run;
    if (t == 255) bsum[blockIdx.x] = ts[255];
}

// Adds inline block-prefix of bsum (<=49 cached loads/thread), writes cur,
// dinv, and off[n] = E.
__global__ void scan3_kernel(int* __restrict__ off, int* __restrict__ cur,
                             const int* __restrict__ cnt, const int* __restrict__ bsum,
                             float* __restrict__ dinv, int n, int E) {
    int i = blockIdx.x * blockDim.x + threadIdx.x;
    if (i == 0) off[n] = E;
    if (i >= n) return;
    int blk = i >> 10;
    int pre = 0;
    for (int b = 0; b < blk; b++) pre += bsum[b];
    int o = off[i] + pre;
    off[i] = o;
    cur[i] = o;
    dinv[i] = rsqrtf((float)cnt[i] + 1.0f);
}

__global__ void fill_kernel(const int* __restrict__ row, const int* __restrict__ col,
                            int* __restrict__ cur, int* __restrict__ csr, int E) {
    int e = blockIdx.x * blockDim.x + threadIdx.x;
    if (e >= E) return;
    int pos = atomicAdd(&cur[col[e]], 1);
    csr[pos] = row[e];
}

// Warp per node, fp16 rows: lane covers 4 cols (uint2 = 4 halves).
__global__ void gather_kernel(const __half* __restrict__ h0,
                              const float* __restrict__ dinv,
                              const int* __restrict__ off,
                              const int* __restrict__ csr,
                              const float* __restrict__ b,
                              __half* __restrict__ h1, int n)
{
    int w = (blockIdx.x * blockDim.x + threadIdx.x) >> 5;
    int lane = threadIdx.x & 31;
    if (w >= n) return;
    float di = dinv[w];
    const uint2* H0 = reinterpret_cast<const uint2*>(h0);   // 32 uint2 per row

    uint2 sv = H0[(size_t)w * 32 + lane];
    float2 s0 = __half22float2(*reinterpret_cast<__half2*>(&sv.x));
    float2 s1 = __half22float2(*reinterpret_cast<__half2*>(&sv.y));
    float dii = di * di;
    float a0 = s0.x * dii, a1 = s0.y * dii, a2 = s1.x * dii, a3 = s1.y * dii;

    int j = off[w], end = off[w + 1];
    for (; j + 3 < end; j += 4) {
        int r0 = csr[j], r1 = csr[j + 1], r2 = csr[j + 2], r3 = csr[j + 3];
        float n0 = dinv[r0] * di, n1 = dinv[r1] * di;
        float n2 = dinv[r2] * di, n3 = dinv[r3] * di;
        uint2 v0 = H0[(size_t)r0 * 32 + lane];
        uint2 v1 = H0[(size_t)r1 * 32 + lane];
        uint2 v2 = H0[(size_t)r2 * 32 + lane];
        uint2 v3 = H0[(size_t)r3 * 32 + lane];
        float2 p, q;
        p = __half22float2(*reinterpret_cast<__half2*>(&v0.x));
        q = __half22float2(*reinterpret_cast<__half2*>(&v0.y));
        a0 += n0 * p.x; a1 += n0 * p.y; a2 += n0 * q.x; a3 += n0 * q.y;
        p = __half22float2(*reinterpret_cast<__half2*>(&v1.x));
        q = __half22float2(*reinterpret_cast<__half2*>(&v1.y));
        a0 += n1 * p.x; a1 += n1 * p.y; a2 += n1 * q.x; a3 += n1 * q.y;
        p = __half22float2(*reinterpret_cast<__half2*>(&v2.x));
        q = __half22float2(*reinterpret_cast<__half2*>(&v2.y));
        a0 += n2 * p.x; a1 += n2 * p.y; a2 += n2 * q.x; a3 += n2 * q.y;
        p = __half22float2(*reinterpret_cast<__half2*>(&v3.x));
        q = __half22float2(*reinterpret_cast<__half2*>(&v3.y));
        a0 += n3 * p.x; a1 += n3 * p.y; a2 += n3 * q.x; a3 += n3 * q.y;
    }
    for (; j < end; j++) {
        int r = csr[j];
        float nr = dinv[r] * di;
        uint2 v = H0[(size_t)r * 32 + lane];
        float2 p = __half22float2(*reinterpret_cast<__half2*>(&v.x));
        float2 q = __half22float2(*reinterpret_cast<__half2*>(&v.y));
        a0 += nr * p.x; a1 += nr * p.y; a2 += nr * q.x; a3 += nr * q.y;
    }
    float4 bb = reinterpret_cast<const float4*>(b)[lane];
    uint2 outv;
    outv.x = pack_h2(a0 + bb.x, a1 + bb.y);
    outv.y = pack_h2(a2 + bb.z, a3 + bb.w);
    reinterpret_cast<uint2*>(h1)[(size_t)w * 32 + lane] = outv;
}

// ---------------------------------------------------------------------------
// Launcher
// ---------------------------------------------------------------------------
extern "C" void kernel_launch(void* const* d_in, const int* in_sizes, int n_in,
                              void* d_out, int out_size)
{
    const float* x      = (const float*)d_in[0];
    const int*   eidx   = (const int*)  d_in[1];
    const float* gcn_w  = (const float*)d_in[2];
    const float* gcn_b  = (const float*)d_in[3];
    const float* enc_w  = (const float*)d_in[4];
    const float* enc_b  = (const float*)d_in[5];
    const float* mean_w = (const float*)d_in[6];
    const float* mean_b = (const float*)d_in[7];
    const float* std_w  = (const float*)d_in[8];
    const float* std_b  = (const float*)d_in[9];
    float* out = (float*)d_out;

    const int n  = in_sizes[0] / ND;          // 50000
    const int E  = in_sizes[1] / 2;           // 800000
    const int NE = n * ND;

    __half *h0, *h1, *ws;
    float *dinv;
    int *cnt, *off, *cur, *csr, *bsum;
    cudaGetSymbolAddress((void**)&h0,   g_h0);
    cudaGetSymbolAddress((void**)&h1,   g_h1);
    cudaGetSymbolAddress((void**)&dinv, g_dinv);
    cudaGetSymbolAddress((void**)&cnt,  g_cnt);
    cudaGetSymbolAddress((void**)&off,  g_off);
    cudaGetSymbolAddress((void**)&cur,  g_cur);
    cudaGetSymbolAddress((void**)&csr,  g_csr);
    cudaGetSymbolAddress((void**)&bsum, g_bsum);
    cudaGetSymbolAddress((void**)&ws,   g_wsplit);

    cudaFuncSetAttribute(gemm_f32in, cudaFuncAttributeMaxDynamicSharedMemorySize, SMEM_G);
    cudaFuncSetAttribute(mega,       cudaFuncAttributeMaxDynamicSharedMemorySize, SMEM_G);

    const int gblocks = (n + 63) / 64;        // 782
    const int nblk = (n + 1023) / 1024;

#define WLHI(l) (ws + (size_t)(l) * 2 * MAT_ELEMS)

    // Fork: CSR build on side stream, overlapping wprep + GEMM0.
    cudaStream_t s2;
    cudaStreamCreateWithFlags(&s2, cudaStreamNonBlocking);
    cudaEvent_t ev1, ev2;
    cudaEventCreateWithFlags(&ev1, cudaEventDisableTiming);
    cudaEventCreateWithFlags(&ev2, cudaEventDisableTiming);

    cudaEventRecord(ev1, 0);
    cudaStreamWaitEvent(s2, ev1, 0);
    cudaMemsetAsync(cnt, 0, n * sizeof(int), s2);
    cnt_accum_kernel<<<(E + 255) / 256, 256, 0, s2>>>(eidx + E, cnt, E);
    scan1_kernel<<<nblk, 256, 0, s2>>>(cnt, off, bsum, n);
    scan3_kernel<<<(n + 255) / 256, 256, 0, s2>>>(off, cur, cnt, bsum, dinv, n, E);
    fill_kernel<<<(E + 255) / 256, 256, 0, s2>>>(eidx, eidx + E, cur, csr, E);
    cudaEventRecord(ev2, s2);

    // Main stream: weight prep + GEMM0 concurrently with CSR build.
    {
        dim3 grid(ND * ND / 256, NLAYER);
        wprep_kernel<<<grid, 256>>>(gcn_w, enc_w, mean_w, std_w, ws);
    }
    gemm_f32in<<<gblocks, 256, SMEM_G>>>(x, WLHI(0), h0, n);

    // Join, then gather (h0 -> h1, + gcn_b).
    cudaStreamWaitEvent(0, ev2, 0);
    gather_kernel<<<(n * 32 + 255) / 256, 256>>>(h0, dinv, off, csr, gcn_b, h1, n);

    // Fused: 5 encoder layers + heads + z, one launch @ 2 CTAs/SM.
    mega<<<gblocks, 256, SMEM_G>>>(h1, ws, enc_b, mean_b, std_b,
                                   out, out + NE, out + 2 * NE, n);

    cudaEventDestroy(ev1);
    cudaEventDestroy(ev2);
    cudaStreamDestroy(s2);
}